// round 14
// baseline (speedup 1.0000x reference)
#include <cuda_runtime.h>
#include <cuda_bf16.h>
#include <stdint.h>
#include <math.h>

#define Bd   8
#define Pd   5
#define Qd   75
#define Cd   640
#define HWd  49
#define BQd  (Bd*Qd)          // 600
#define NMAT (Bd*Qd*Pd)       // 3000
#define IMG  (Cd*HWd)         // 31360
#define SMATS   2404
#define TEMPER  12.5f
#define INV_EPS 20.0f
#define S_ITERS 100

#define Nn   248
#define CP   320
#define MROWS (Qd*HWd)        // 3675
#define MT_PER_B 58
#define NGBLK (Bd*MT_PER_B*2) // 928
#define VP2  56               // padded sinkhorn vector length (14 float4)

// ---------------- scratch ----------------
__device__ uint32_t g_qbf_hi[(size_t)BQd*HWd*CP];
__device__ uint32_t g_qbf_lo[(size_t)BQd*HWd*CP];
__device__ uint32_t g_sbf_hi[(size_t)Bd*Nn*CP];
__device__ uint32_t g_sbf_lo[(size_t)Bd*Nn*CP];
__device__ float g_sgap[Bd*Pd*Cd];
__device__ float g_qgap[BQd*Cd];
__device__ float g_ma[NMAT*HWd];
__device__ float g_mb[NMAT*HWd];
__device__ float g_S[(size_t)NMAT*SMATS];
__device__ float g_logits[NMAT];

// ---------------- helpers ----------------
__device__ __forceinline__ float2 ffma2(float2 a, float2 b, float2 c) {
    float2 d;
    asm("fma.rn.f32x2 %0, %1, %2, %3;"
        : "=l"(reinterpret_cast<unsigned long long&>(d))
        : "l"(reinterpret_cast<unsigned long long&>(a)),
          "l"(reinterpret_cast<unsigned long long&>(b)),
          "l"(reinterpret_cast<unsigned long long&>(c)));
    return d;
}
__device__ __forceinline__ void mma16816(float* d,
    uint32_t a0, uint32_t a1, uint32_t a2, uint32_t a3,
    uint32_t b0, uint32_t b1) {
    asm volatile("mma.sync.aligned.m16n8k16.row.col.f32.bf16.bf16.f32 "
        "{%0,%1,%2,%3}, {%4,%5,%6,%7}, {%8,%9}, {%0,%1,%2,%3};"
        : "+f"(d[0]), "+f"(d[1]), "+f"(d[2]), "+f"(d[3])
        : "r"(a0), "r"(a1), "r"(a2), "r"(a3), "r"(b0), "r"(b1));
}
__device__ __forceinline__ uint32_t smem_u32(const void* p) {
    uint32_t a;
    asm("{ .reg .u64 t; cvta.to.shared.u64 t, %1; cvt.u32.u64 %0, t; }" : "=r"(a) : "l"(p));
    return a;
}
__device__ __forceinline__ void cp_async16(uint32_t dst, const void* src) {
    asm volatile("cp.async.cg.shared.global [%0], [%1], 16;" :: "r"(dst), "l"(src));
}
#define CP_COMMIT() asm volatile("cp.async.commit_group;" ::: "memory")
#define CP_WAIT1()  asm volatile("cp.async.wait_group 1;" ::: "memory")
#define CP_WAIT0()  asm volatile("cp.async.wait_group 0;" ::: "memory")

// 28-element half-dot: 7 float4 of K (regs) x 7 float4 of v (SMEM broadcast).
__device__ __forceinline__ float dot7(const float4* K, const float4* v4) {
    float2 a0 = make_float2(0,0), a1 = a0, a2 = a0, a3 = a0;
    #pragma unroll
    for (int j = 0; j < 6; j += 2) {
        float4 k0 = K[j], k1 = K[j+1];
        float4 v0 = v4[j], v1 = v4[j+1];
        a0 = ffma2(make_float2(k0.x, k0.y), make_float2(v0.x, v0.y), a0);
        a1 = ffma2(make_float2(k0.z, k0.w), make_float2(v0.z, v0.w), a1);
        a2 = ffma2(make_float2(k1.x, k1.y), make_float2(v1.x, v1.y), a2);
        a3 = ffma2(make_float2(k1.z, k1.w), make_float2(v1.z, v1.w), a3);
    }
    float4 k0 = K[6], v0 = v4[6];
    a0 = ffma2(make_float2(k0.x, k0.y), make_float2(v0.x, v0.y), a0);
    a1 = ffma2(make_float2(k0.z, k0.w), make_float2(v0.z, v0.w), a1);
    return ((a0.x + a0.y) + (a1.x + a1.y)) + ((a2.x + a2.y) + (a3.x + a3.y));
}

extern __shared__ float sh_dyn[];

// ---------------- kernel 0: support prep (full-stage; only 40 blocks) -------
#define PREPS_SMEM ((IMG + 128)*4)
__global__ void __launch_bounds__(512) prep_sup(const float* __restrict__ sup) {
    float* img   = sh_dyn;
    float* cmean = sh_dyn + IMG;
    float* crn   = cmean + 64;
    const int t = threadIdx.x;
    const int bp = blockIdx.x, b = bp / Pd, p = bp % Pd;

    const float4* s4 = (const float4*)(sup + (size_t)bp*IMG);
    float4* d4 = (float4*)img;
    for (int i = t; i < IMG/4; i += 512) d4[i] = s4[i];
    __syncthreads();

    const int w = t >> 5, lane = t & 31;
    for (int m = w; m < HWd; m += 16) {
        float s = 0.f;
        for (int c = lane; c < Cd; c += 32) s += img[c*HWd + m];
        #pragma unroll
        for (int o = 16; o; o >>= 1) s += __shfl_xor_sync(0xffffffffu, s, o);
        float mean = s * (1.0f/Cd);
        float ss = 0.f;
        for (int c = lane; c < Cd; c += 32) { float d = img[c*HWd + m] - mean; ss += d*d; }
        #pragma unroll
        for (int o = 16; o; o >>= 1) ss += __shfl_xor_sync(0xffffffffu, ss, o);
        if (lane == 0) { cmean[m] = mean; crn[m] = 1.0f / fmaxf(sqrtf(ss), 1e-8f); }
    }
    __syncthreads();

    for (int c = t; c < Cd; c += 512) {
        const float* pp = img + c*HWd;
        float s = 0.f;
        #pragma unroll 7
        for (int m = 0; m < HWd; m++) s += pp[m];
        g_sgap[(size_t)bp*Cd + c] = s * (1.0f/HWd);
    }

    for (int j = t; j < HWd*CP; j += 512) {
        int nn = j / CP, cp = j - nn*CP, c = 2*cp;
        float v0 = (img[c*HWd + nn]     - cmean[nn]) * crn[nn];
        float v1 = (img[(c+1)*HWd + nn] - cmean[nn]) * crn[nn];
        __nv_bfloat162 hi2 = __floats2bfloat162_rn(v0, v1);
        __nv_bfloat162 lo2 = __floats2bfloat162_rn(v0 - __bfloat162float(hi2.x),
                                                   v1 - __bfloat162float(hi2.y));
        size_t o = ((size_t)b*Nn + p*HWd + nn)*CP + cp;
        g_sbf_hi[o] = *reinterpret_cast<uint32_t*>(&hi2);
        g_sbf_lo[o] = *reinterpret_cast<uint32_t*>(&lo2);
    }
}

// ---------------- kernel 1: tiled query prep (28 KB smem, 6 blocks/SM) ------
// 320 threads. Phase A: 10 tiles of 64 channels -> stats + GAP + w1.
// Phase B: finalize cmean/crn/marginals. Phase C: re-stage tiles, bf16 hi/lo.
#define TSTR 51
__global__ void __launch_bounds__(320) prep_qry(const float* __restrict__ qry, int bq0) {
    __shared__ float sg[Pd*Cd];          // 12.8 KB
    __shared__ float tile[64*TSTR];      // 13.1 KB
    __shared__ float w1a[Pd*HWd];
    __shared__ float colsum[HWd], colsq[HWd], cmean[HWd], crn[HWd], rs[Pd];

    const int t = threadIdx.x;
    const int bq = bq0 + blockIdx.x, b = bq / Qd;
    const float* src = qry + (size_t)bq*IMG;

    for (int i = t; i < Pd*Cd; i += 320) sg[i] = g_sgap[(size_t)b*Pd*Cd + i];
    __syncthreads();

    const bool isw1  = t < Pd*HWd;                   // 0..244
    const int  p = t / HWd, m = t - p*HWd;
    const bool isgap = (t >= 245 && t < 309);        // 64 gap threads
    const int  ccg = t - 245;
    float w1t = 0.f, cs = 0.f, cq = 0.f;

    // Phase A
    for (int tl = 0; tl < 10; tl++) {
        const int c0 = tl*64;
        for (int i = t; i < 64*HWd; i += 320) {
            int cc = i / HWd, mm = i - cc*HWd;
            tile[cc*TSTR + mm] = src[c0*HWd + i];
        }
        __syncthreads();
        if (isw1) {
            const float* sgp = sg + p*Cd + c0;
            if (t < HWd) {
                #pragma unroll 4
                for (int cc = 0; cc < 64; cc++) {
                    float v = tile[cc*TSTR + m];
                    w1t += v * sgp[cc];
                    cs += v; cq += v*v;
                }
            } else {
                #pragma unroll 8
                for (int cc = 0; cc < 64; cc++)
                    w1t += tile[cc*TSTR + m] * sgp[cc];
            }
        } else if (isgap) {
            float g = 0.f;
            #pragma unroll 7
            for (int mm = 0; mm < HWd; mm++) g += tile[ccg*TSTR + mm];
            g_qgap[(size_t)bq*Cd + c0 + ccg] = g * (1.0f/HWd);
        }
        __syncthreads();
    }

    // Phase B: finalize
    if (isw1) {
        w1a[t] = (fmaxf(w1t, 0.f) + 1e-3f) + 1e-5f;
        if (t < HWd) { colsum[t] = cs; colsq[t] = cq; }
    }
    __syncthreads();
    if (t < HWd) {
        float mean = colsum[t] * (1.0f/Cd);
        cmean[t] = mean;
        float var = colsq[t] - Cd*mean*mean;
        crn[t] = 1.0f / fmaxf(sqrtf(fmaxf(var, 0.f)), 1e-8f);
    }
    if (t >= 64 && t < 64 + Pd) {
        int pp = t - 64;
        float s = 0.f;
        for (int k = 0; k < HWd; k++) s += w1a[pp*HWd + k];
        rs[pp] = 1.0f / s;
    }
    __syncthreads();
    if (isw1) g_ma[((size_t)bq*Pd + p)*HWd + m] = w1a[t] * rs[p];

    // Phase C: bf16 hi/lo write (re-stage from L2)
    for (int tl = 0; tl < 10; tl++) {
        const int c0 = tl*64;
        __syncthreads();
        for (int i = t; i < 64*HWd; i += 320) {
            int cc = i / HWd, mm = i - cc*HWd;
            tile[cc*TSTR + mm] = src[c0*HWd + i];
        }
        __syncthreads();
        for (int j = t; j < HWd*32; j += 320) {
            int mm = j >> 5, cpl = j & 31;
            float v0 = (tile[(2*cpl)*TSTR + mm]   - cmean[mm]) * crn[mm];
            float v1 = (tile[(2*cpl+1)*TSTR + mm] - cmean[mm]) * crn[mm];
            __nv_bfloat162 hi2 = __floats2bfloat162_rn(v0, v1);
            __nv_bfloat162 lo2 = __floats2bfloat162_rn(v0 - __bfloat162float(hi2.x),
                                                       v1 - __bfloat162float(hi2.y));
            size_t o = ((size_t)bq*HWd + mm)*CP + (c0 >> 1) + cpl;
            g_qbf_hi[o] = *reinterpret_cast<uint32_t*>(&hi2);
            g_qbf_lo[o] = *reinterpret_cast<uint32_t*>(&lo2);
        }
    }
}

// ---------------- kernel 2: w2 marginals (40 blocks) ----------------
__global__ void __launch_bounds__(256) w2_kernel(const float* __restrict__ sup) {
    __shared__ float sch[32*52];
    __shared__ float gch2[32*76];
    __shared__ float wb[Qd*HWd];
    __shared__ float rsum[Qd];
    const int t = threadIdx.x;
    const int bp = blockIdx.x, b = bp / Pd, p = bp % Pd;
    for (int i = t; i < 1664; i += 256) sch[i] = 0.f;
    for (int i = t; i < 2432; i += 256) gch2[i] = 0.f;

    const int tx = t % 13, ty = t / 13;
    const bool act = t < 247;
    float2 acc2[4][2];
    #pragma unroll
    for (int i = 0; i < 4; i++) { acc2[i][0] = make_float2(0,0); acc2[i][1] = make_float2(0,0); }
    __syncthreads();

    for (int ch = 0; ch < 20; ch++) {
        for (int i = t; i < 32*HWd; i += 256) {
            int cc = i / HWd, n = i - cc*HWd;
            sch[cc*52 + n] = sup[(size_t)bp*IMG + ch*(32*HWd) + i];
        }
        for (int i = t; i < Qd*32; i += 256) {
            int q = i >> 5, cc = i & 31;
            gch2[cc*76 + q] = g_qgap[((size_t)b*Qd + q)*Cd + ch*32 + cc];
        }
        __syncthreads();
        if (act) {
            #pragma unroll 8
            for (int cc = 0; cc < 32; cc++) {
                float4 s4 = *(const float4*)&sch[cc*52 + tx*4];
                float4 g4 = *(const float4*)&gch2[cc*76 + ty*4];
                float2 sA = make_float2(s4.x, s4.y), sB = make_float2(s4.z, s4.w);
                float g[4] = {g4.x, g4.y, g4.z, g4.w};
                #pragma unroll
                for (int qi = 0; qi < 4; qi++) {
                    float2 gg = make_float2(g[qi], g[qi]);
                    acc2[qi][0] = ffma2(gg, sA, acc2[qi][0]);
                    acc2[qi][1] = ffma2(gg, sB, acc2[qi][1]);
                }
            }
        }
        __syncthreads();
    }
    if (act) {
        #pragma unroll
        for (int qi = 0; qi < 4; qi++) {
            int q = ty*4 + qi;
            if (q >= Qd) continue;
            float vals[4] = {acc2[qi][0].x, acc2[qi][0].y, acc2[qi][1].x, acc2[qi][1].y};
            #pragma unroll
            for (int e = 0; e < 4; e++) {
                int n = tx*4 + e;
                if (n < HWd)
                    wb[q*HWd + n] = (fmaxf(vals[e], 0.f) + 1e-3f) + 1e-5f;
            }
        }
    }
    __syncthreads();
    if (t < Qd) {
        float s = 0.f;
        for (int k = 0; k < HWd; k++) s += wb[t*HWd + k];
        rsum[t] = 1.0f / s;
    }
    __syncthreads();
    for (int i = t; i < Qd*HWd; i += 256) {
        int q = i / HWd;
        g_mb[(((size_t)b*Qd + q)*Pd + p)*HWd + (i - q*HWd)] = wb[i] * rsum[q];
    }
}

// ---------------- kernel 3: packed-row cp.async double-buffered MMA GEMM ----
#define RS    36
#define A_LO_W (64*RS)
#define B_HI_W (128*RS)
#define BUF_W  (384*RS)
#define GEMM_SMEM (2*BUF_W*4)

__global__ void __launch_bounds__(256) sgemm_mma_kernel() {
    const int t = threadIdx.x;
    const int blk = blockIdx.x;
    const int b  = blk / (MT_PER_B*2);
    const int rem = blk - b*(MT_PER_B*2);
    const int mt = rem >> 1, nt = rem & 1;
    const int warp = t >> 5, lane = t & 31;
    const int wm = warp >> 2, wn = warp & 3;
    const int gid = lane >> 2, tid4 = lane & 3;

    const uint32_t smb = smem_u32(sh_dyn);
    const uint32_t* smw = (const uint32_t*)sh_dyn;

    const uint4* qh = (const uint4*)g_qbf_hi;
    const uint4* ql = (const uint4*)g_qbf_lo;
    const uint4* shv = (const uint4*)g_sbf_hi;
    const uint4* slv = (const uint4*)g_sbf_lo;

    float acc[2][4][4];
    #pragma unroll
    for (int i = 0; i < 2; i++)
        #pragma unroll
        for (int j = 0; j < 4; j++)
            #pragma unroll
            for (int k = 0; k < 4; k++) acc[i][j][k] = 0.f;

    auto stage = [&](int ch, int bufsel) {
        const uint32_t dbase = smb + (uint32_t)bufsel*(BUF_W*4);
        #pragma unroll
        for (int k = 0; k < 4; k++) {
            int i = t + k*256;
            int arr = i >> 9, remx = i & 511, row = remx >> 3, seg = remx & 7;
            int R = mt*64 + row; if (R > MROWS-1) R = MROWS-1;
            const uint4* s = (arr ? ql : qh) + ((size_t)b*MROWS + R)*80 + ch*8 + seg;
            cp_async16(dbase + (uint32_t)(arr*A_LO_W + row*RS + seg*4)*4, s);
        }
        #pragma unroll
        for (int k = 0; k < 8; k++) {
            int i = t + k*256;
            int arr = i >> 10, remx = i & 1023, row = remx >> 3, seg = remx & 7;
            int N0 = nt*128 + row; if (N0 > Nn-1) N0 = Nn-1;
            const uint4* s = (arr ? slv : shv) + ((size_t)b*Nn + N0)*80 + ch*8 + seg;
            cp_async16(dbase + (uint32_t)(B_HI_W + arr*(B_HI_W) + row*RS + seg*4)*4, s);
        }
    };

    stage(0, 0);
    CP_COMMIT();

    #pragma unroll 1
    for (int ch = 0; ch < 10; ch++) {
        if (ch < 9) { stage(ch+1, (ch+1) & 1); CP_COMMIT(); CP_WAIT1(); }
        else        { CP_WAIT0(); }
        __syncthreads();

        const uint32_t* bw = smw + (ch & 1)*BUF_W;
        #pragma unroll
        for (int ks = 0; ks < 4; ks++) {
            uint32_t ahf[2][4], alf[2][4];
            #pragma unroll
            for (int ms = 0; ms < 2; ms++) {
                int r0 = wm*32 + ms*16 + gid;
                int w0 = r0*RS + tid4 + ks*8;
                int w1 = (r0+8)*RS + tid4 + ks*8;
                ahf[ms][0] = bw[w0];        ahf[ms][1] = bw[w1];
                ahf[ms][2] = bw[w0+4];      ahf[ms][3] = bw[w1+4];
                alf[ms][0] = bw[A_LO_W+w0]; alf[ms][1] = bw[A_LO_W+w1];
                alf[ms][2] = bw[A_LO_W+w0+4]; alf[ms][3] = bw[A_LO_W+w1+4];
            }
            #pragma unroll
            for (int ns = 0; ns < 4; ns++) {
                int n0 = wn*32 + ns*8 + gid;
                int wb = B_HI_W + n0*RS + tid4 + ks*8;
                uint32_t bh0 = bw[wb], bh1 = bw[wb+4];
                uint32_t bl0 = bw[wb+B_HI_W], bl1 = bw[wb+4+B_HI_W];
                #pragma unroll
                for (int ms = 0; ms < 2; ms++) {
                    mma16816(acc[ms][ns], ahf[ms][0], ahf[ms][1], ahf[ms][2], ahf[ms][3], bh0, bh1);
                    mma16816(acc[ms][ns], ahf[ms][0], ahf[ms][1], ahf[ms][2], ahf[ms][3], bl0, bl1);
                    mma16816(acc[ms][ns], alf[ms][0], alf[ms][1], alf[ms][2], alf[ms][3], bh0, bh1);
                }
            }
        }
        __syncthreads();
    }

    #pragma unroll
    for (int ms = 0; ms < 2; ms++) {
        #pragma unroll
        for (int half = 0; half < 2; half++) {
            int R = mt*64 + wm*32 + ms*16 + gid + half*8;
            if (R >= MROWS) continue;
            int q = R / HWd, mm = R - q*HWd;
            float* dstq = g_S + ((size_t)(b*Qd + q)*Pd)*SMATS + mm*HWd;
            #pragma unroll
            for (int ns = 0; ns < 4; ns++) {
                #pragma unroll
                for (int e = 0; e < 2; e++) {
                    int C = nt*128 + wn*32 + ns*8 + tid4*2 + e;
                    if (C < Pd*HWd) {
                        int p = C / HWd, nn = C - p*HWd;
                        dstq[(size_t)p*SMATS + nn] = acc[ms][ns][half*2 + e];
                    }
                }
            }
        }
    }
}

// ---------------- kernel 4: pair-split Sinkhorn (early exit tau=1e-5) ----
__global__ void __launch_bounds__(128, 1) sinkhorn_kernel() {
    __shared__ __align__(16) float Ksh[VP2*VP2];
    __shared__ __align__(16) float ush[VP2];
    __shared__ __align__(16) float vsh[VP2];
    __shared__ float red[4];

    const int t = threadIdx.x;
    const int idx = blockIdx.x;
    const float* Sg = g_S + (size_t)idx*SMATS;

    float lmax = -1e30f;
    for (int i = t; i < HWd*HWd; i += 128) lmax = fmaxf(lmax, Sg[i]);
    #pragma unroll
    for (int o = 16; o; o >>= 1) lmax = fmaxf(lmax, __shfl_xor_sync(0xffffffffu, lmax, o));
    if ((t & 31) == 0) red[t >> 5] = lmax;
    for (int i = t; i < VP2*VP2; i += 128) Ksh[i] = 0.f;
    if (t < VP2) { vsh[t] = (t < HWd) ? 1.0f : 0.f; ush[t] = 0.f; }
    __syncthreads();
    const float Smax = fmaxf(fmaxf(red[0], red[1]), fmaxf(red[2], red[3]));

    for (int i = t; i < HWd*HWd; i += 128) {
        int m = i / HWd, n = i - m*HWd;
        Ksh[m*VP2 + n] = __expf((Sg[i] - Smax) * INV_EPS);
    }
    __syncthreads();

    const int m = t >> 1, h = t & 1;
    const bool act = m < HWd;
    float4 Kr[7], Kc[7];
    #pragma unroll
    for (int j = 0; j < 7; j++) {
        Kr[j] = make_float4(0.f, 0.f, 0.f, 0.f);
        Kc[j] = make_float4(0.f, 0.f, 0.f, 0.f);
    }
    float am = 0.f, bn = 0.f;
    if (act) {
        const float4* kr4 = (const float4*)(Ksh + m*VP2) + h*7;
        #pragma unroll
        for (int j = 0; j < 7; j++) Kr[j] = kr4[j];
        #pragma unroll
        for (int j = 0; j < 7; j++) {
            int e = h*28 + 4*j;
            Kc[j] = make_float4(Ksh[e*VP2 + m], Ksh[(e+1)*VP2 + m],
                                Ksh[(e+2)*VP2 + m], Ksh[(e+3)*VP2 + m]);
        }
        am = g_ma[(size_t)idx*HWd + m];
        bn = g_mb[(size_t)idx*HWd + m];
    }
    const float4* ub = (const float4*)ush + h*7;
    const float4* vb = (const float4*)vsh + h*7;

    float uprev = 1e30f, vprev = 1e30f;
    #pragma unroll 1
    for (int it = 0; it < S_ITERS; it++) {
        float s = dot7(Kr, vb);
        s += __shfl_xor_sync(0xffffffffu, s, 1);
        float u = __fdividef(am, s);
        if (act && h == 0) ush[m] = u;
        __syncthreads();
        float s2 = dot7(Kc, ub);
        s2 += __shfl_xor_sync(0xffffffffu, s2, 1);
        float v = __fdividef(bn, s2);
        if (act && h == 0) vsh[m] = v;
        if ((it & 3) == 3) {
            bool ok = (!act) || (fabsf(u - uprev) <= 1e-5f*fabsf(u) &&
                                 fabsf(v - vprev) <= 1e-5f*fabsf(v));
            uprev = u; vprev = v;
            if (__syncthreads_and(ok)) break;
        } else {
            __syncthreads();
        }
    }

    float part = 0.f;
    for (int i = t; i < HWd*HWd; i += 128) {
        int mm = i / HWd, nn = i - mm*HWd;
        part += Sg[i] * Ksh[mm*VP2 + nn] * ush[mm] * vsh[nn];
    }
    #pragma unroll
    for (int o = 16; o; o >>= 1) part += __shfl_xor_sync(0xffffffffu, part, o);
    if ((t & 31) == 0) red[t >> 5] = part;
    __syncthreads();
    if (t == 0) g_logits[idx] = TEMPER * ((red[0] + red[1]) + (red[2] + red[3]));
}

// ---------------- kernel 5: cross-entropy loss ----------------
__global__ void loss_kernel(const int* __restrict__ qy, float* __restrict__ out) {
    __shared__ float red[8];
    const int t = threadIdx.x;
    float s = 0.f;
    for (int r = t; r < BQd; r += 256) {
        float l[Pd];
        #pragma unroll
        for (int k = 0; k < Pd; k++) l[k] = g_logits[r*Pd + k];
        float mx = l[0];
        #pragma unroll
        for (int k = 1; k < Pd; k++) mx = fmaxf(mx, l[k]);
        float se = 0.f;
        #pragma unroll
        for (int k = 0; k < Pd; k++) se += expf(l[k] - mx);
        float lse = mx + logf(se);
        s += lse - l[qy[r]];
    }
    #pragma unroll
    for (int o = 16; o; o >>= 1) s += __shfl_xor_sync(0xffffffffu, s, o);
    if ((t & 31) == 0) red[t >> 5] = s;
    __syncthreads();
    if (t == 0) {
        float tot = 0.f;
        #pragma unroll
        for (int i = 0; i < 8; i++) tot += red[i];
        out[0] = tot * (1.0f / BQd);
    }
}

// ---------------- launch ---------------------------------------------------
extern "C" void kernel_launch(void* const* d_in, const int* in_sizes, int n_in,
                              void* d_out, int out_size) {
    const float* sup = (const float*)d_in[0];
    const float* qry = (const float*)d_in[1];
    const int*   qy  = (const int*)d_in[3];
    float* out = (float*)d_out;

    cudaFuncSetAttribute(prep_sup, cudaFuncAttributeMaxDynamicSharedMemorySize, PREPS_SMEM);
    cudaFuncSetAttribute(sgemm_mma_kernel, cudaFuncAttributeMaxDynamicSharedMemorySize, GEMM_SMEM);

    prep_sup<<<Bd*Pd, 512, PREPS_SMEM>>>(sup);
    prep_qry<<<200, 320>>>(qry, 0);
    prep_qry<<<200, 320>>>(qry, 200);
    prep_qry<<<200, 320>>>(qry, 400);   // 4th launch -> profiled next round
    w2_kernel<<<Bd*Pd, 256>>>(sup);
    sgemm_mma_kernel<<<NGBLK, 256, GEMM_SMEM>>>();
    sinkhorn_kernel<<<NMAT, 128>>>();
    loss_kernel<<<1, 256>>>(qy, out);
}

// round 15
// speedup vs baseline: 1.2512x; 1.2512x over previous
#include <cuda_runtime.h>
#include <cuda_bf16.h>
#include <stdint.h>
#include <math.h>

#define Bd   8
#define Pd   5
#define Qd   75
#define Cd   640
#define HWd  49
#define BQd  (Bd*Qd)          // 600
#define NMAT (Bd*Qd*Pd)       // 3000
#define IMG  (Cd*HWd)         // 31360
#define SMATS   2404
#define TEMPER  12.5f
#define INV_EPS 20.0f
#define S_ITERS 100

#define Nn   248
#define CP   320
#define MROWS (Qd*HWd)        // 3675
#define MT_PER_B 58
#define NGBLK (Bd*MT_PER_B*2) // 928
#define VP2  56
#define TSTR 51

// ---------------- scratch ----------------
__device__ uint32_t g_qbf_hi[(size_t)BQd*HWd*CP];
__device__ uint32_t g_qbf_lo[(size_t)BQd*HWd*CP];
__device__ uint32_t g_sbf_hi[(size_t)Bd*Nn*CP];
__device__ uint32_t g_sbf_lo[(size_t)Bd*Nn*CP];
__device__ float g_sgap[Bd*Pd*Cd];
__device__ float g_qgap[BQd*Cd];
__device__ float g_ma[NMAT*HWd];
__device__ float g_mb[NMAT*HWd];
__device__ float g_S[(size_t)NMAT*SMATS];
__device__ float g_logits[NMAT];

// ---------------- helpers ----------------
__device__ __forceinline__ float2 ffma2(float2 a, float2 b, float2 c) {
    float2 d;
    asm("fma.rn.f32x2 %0, %1, %2, %3;"
        : "=l"(reinterpret_cast<unsigned long long&>(d))
        : "l"(reinterpret_cast<unsigned long long&>(a)),
          "l"(reinterpret_cast<unsigned long long&>(b)),
          "l"(reinterpret_cast<unsigned long long&>(c)));
    return d;
}
__device__ __forceinline__ void mma16816(float* d,
    uint32_t a0, uint32_t a1, uint32_t a2, uint32_t a3,
    uint32_t b0, uint32_t b1) {
    asm volatile("mma.sync.aligned.m16n8k16.row.col.f32.bf16.bf16.f32 "
        "{%0,%1,%2,%3}, {%4,%5,%6,%7}, {%8,%9}, {%0,%1,%2,%3};"
        : "+f"(d[0]), "+f"(d[1]), "+f"(d[2]), "+f"(d[3])
        : "r"(a0), "r"(a1), "r"(a2), "r"(a3), "r"(b0), "r"(b1));
}
__device__ __forceinline__ uint32_t smem_u32(const void* p) {
    uint32_t a;
    asm("{ .reg .u64 t; cvta.to.shared.u64 t, %1; cvt.u32.u64 %0, t; }" : "=r"(a) : "l"(p));
    return a;
}
__device__ __forceinline__ void cp_async16(uint32_t dst, const void* src) {
    asm volatile("cp.async.cg.shared.global [%0], [%1], 16;" :: "r"(dst), "l"(src));
}
#define CP_COMMIT() asm volatile("cp.async.commit_group;" ::: "memory")
#define CP_WAIT1()  asm volatile("cp.async.wait_group 1;" ::: "memory")
#define CP_WAIT0()  asm volatile("cp.async.wait_group 0;" ::: "memory")

__device__ __forceinline__ float dot7(const float4* K, const float4* v4) {
    float2 a0 = make_float2(0,0), a1 = a0, a2 = a0, a3 = a0;
    #pragma unroll
    for (int j = 0; j < 6; j += 2) {
        float4 k0 = K[j], k1 = K[j+1];
        float4 v0 = v4[j], v1 = v4[j+1];
        a0 = ffma2(make_float2(k0.x, k0.y), make_float2(v0.x, v0.y), a0);
        a1 = ffma2(make_float2(k0.z, k0.w), make_float2(v0.z, v0.w), a1);
        a2 = ffma2(make_float2(k1.x, k1.y), make_float2(v1.x, v1.y), a2);
        a3 = ffma2(make_float2(k1.z, k1.w), make_float2(v1.z, v1.w), a3);
    }
    float4 k0 = K[6], v0 = v4[6];
    a0 = ffma2(make_float2(k0.x, k0.y), make_float2(v0.x, v0.y), a0);
    a1 = ffma2(make_float2(k0.z, k0.w), make_float2(v0.z, v0.w), a1);
    return ((a0.x + a0.y) + (a1.x + a1.y)) + ((a2.x + a2.y) + (a3.x + a3.y));
}

extern __shared__ float sh_dyn[];

// ---------------- kernel 0: support GAPs only (40 blocks, fast) -------------
#define GAPS_SMEM (IMG*4)
__global__ void __launch_bounds__(512) gaps_sup(const float* __restrict__ sup) {
    float* img = sh_dyn;
    const int bid = blockIdx.x, t = threadIdx.x;
    const float4* s4 = (const float4*)(sup + (size_t)bid*IMG);
    float4* d4 = (float4*)img;
    for (int i = t; i < IMG/4; i += 512) d4[i] = s4[i];
    __syncthreads();
    for (int c = t; c < Cd; c += 512) {
        const float* pp = img + c*HWd;
        float s = 0.f;
        #pragma unroll 7
        for (int m = 0; m < HWd; m++) s += pp[m];
        g_sgap[(size_t)bid*Cd + c] = s * (1.0f/HWd);
    }
}

// ---------------- kernel 1: merged tiled prep (640 blocks, 4/SM) ------------
// blocks 0..39 = (b,p) support; 40..639 = (b,q) query. 512 threads.
// Pass A: 10x64-ch tiles -> stats (+w1 for qry, lane-pair split).
// Pass C: re-stage tiles -> bf16 hi/lo (+GAP for qry).
__global__ void __launch_bounds__(512) prep_merged(const float* __restrict__ sup,
                                                   const float* __restrict__ qry) {
    __shared__ float sg[Pd*Cd];
    __shared__ float tile[64*TSTR];
    __shared__ float w1a[Pd*HWd];
    __shared__ float colsum[HWd], colsq[HWd], cmean[HWd], crn[HWd], rs[Pd];

    const int t = threadIdx.x;
    const int bid = blockIdx.x;
    const bool is_sup = bid < Bd*Pd;
    const int bq = bid - Bd*Pd;
    const float* src = is_sup ? (sup + (size_t)bid*IMG)
                              : (qry + (size_t)bq*IMG);
    if (!is_sup) {
        const int b = bq / Qd;
        for (int i = t; i < Pd*Cd; i += 512) sg[i] = g_sgap[(size_t)b*Pd*Cd + i];
    }

    const int out = t >> 1, h = t & 1;          // pair split
    const int p = out / HWd, m = out - p*HWd;   // valid for out<245
    const bool w1act = (!is_sup) && (t < 490);
    const bool stact = (t < 98);                // stats threads (m = out)
    float w1t = 0.f, cs = 0.f, cq = 0.f;

    // ---- Pass A ----
    for (int tl = 0; tl < 10; tl++) {
        __syncthreads();
        const float4* s4 = (const float4*)(src + tl*3136);
        for (int i = t; i < 784; i += 512) {
            float4 v = s4[i];
            int base = i*4;
            #pragma unroll
            for (int e = 0; e < 4; e++) {
                int idx = base + e, cc = idx / HWd, mm = idx - cc*HWd;
                tile[cc*TSTR + mm] = (&v.x)[e];
            }
        }
        __syncthreads();
        if (w1act) {
            const float* sgp = sg + p*Cd + tl*64 + h*32;
            const float* tp = tile + (h*32)*TSTR + m;
            if (stact) {
                #pragma unroll 8
                for (int j = 0; j < 32; j++) {
                    float v = tp[j*TSTR];
                    w1t += v * sgp[j];
                    cs += v; cq += v*v;
                }
            } else {
                #pragma unroll 8
                for (int j = 0; j < 32; j++)
                    w1t += tp[j*TSTR] * sgp[j];
            }
        } else if (is_sup && stact) {
            const float* tp = tile + (h*32)*TSTR + out;
            #pragma unroll 8
            for (int j = 0; j < 32; j++) {
                float v = tp[j*TSTR];
                cs += v; cq += v*v;
            }
        }
    }

    // combine pairs
    w1t += __shfl_xor_sync(0xffffffffu, w1t, 1);
    cs  += __shfl_xor_sync(0xffffffffu, cs, 1);
    cq  += __shfl_xor_sync(0xffffffffu, cq, 1);
    if (w1act && h == 0) w1a[out] = (fmaxf(w1t, 0.f) + 1e-3f) + 1e-5f;
    if (stact && h == 0) { colsum[out] = cs; colsq[out] = cq; }
    __syncthreads();
    if (t < HWd) {
        float mean = colsum[t] * (1.0f/Cd);
        cmean[t] = mean;
        float var = colsq[t] - Cd*mean*mean;
        crn[t] = 1.0f / fmaxf(sqrtf(fmaxf(var, 0.f)), 1e-8f);
    }
    if (!is_sup && t >= 64 && t < 64 + Pd) {
        int pp = t - 64;
        float s = 0.f;
        for (int k = 0; k < HWd; k++) s += w1a[pp*HWd + k];
        rs[pp] = 1.0f / s;
    }
    __syncthreads();
    if (!is_sup && t < Pd*HWd) {
        int pp = t / HWd;
        g_ma[((size_t)bq*Pd + pp)*HWd + (t - pp*HWd)] = w1a[t] * rs[pp];
    }

    // ---- Pass C: bf16 hi/lo (+ qry GAP) ----
    const int bS = bid / Pd, pS = bid % Pd;   // sup coords
    for (int tl = 0; tl < 10; tl++) {
        __syncthreads();
        const float4* s4 = (const float4*)(src + tl*3136);
        for (int i = t; i < 784; i += 512) {
            float4 v = s4[i];
            int base = i*4;
            #pragma unroll
            for (int e = 0; e < 4; e++) {
                int idx = base + e, cc = idx / HWd, mm = idx - cc*HWd;
                tile[cc*TSTR + mm] = (&v.x)[e];
            }
        }
        __syncthreads();
        if (t < 448) {
            for (int j = t; j < HWd*32; j += 448) {
                int mm = j >> 5, cpl = j & 31;
                float v0 = (tile[(2*cpl)*TSTR + mm]   - cmean[mm]) * crn[mm];
                float v1 = (tile[(2*cpl+1)*TSTR + mm] - cmean[mm]) * crn[mm];
                __nv_bfloat162 hi2 = __floats2bfloat162_rn(v0, v1);
                __nv_bfloat162 lo2 = __floats2bfloat162_rn(v0 - __bfloat162float(hi2.x),
                                                           v1 - __bfloat162float(hi2.y));
                size_t o;
                if (is_sup) o = ((size_t)bS*Nn + pS*HWd + mm)*CP + tl*32 + cpl;
                else        o = ((size_t)bq*HWd + mm)*CP + tl*32 + cpl;
                if (is_sup) {
                    g_sbf_hi[o] = *reinterpret_cast<uint32_t*>(&hi2);
                    g_sbf_lo[o] = *reinterpret_cast<uint32_t*>(&lo2);
                } else {
                    g_qbf_hi[o] = *reinterpret_cast<uint32_t*>(&hi2);
                    g_qbf_lo[o] = *reinterpret_cast<uint32_t*>(&lo2);
                }
            }
        } else if (!is_sup) {
            int c = t - 448;     // 0..63
            const float* tp = tile + c*TSTR;
            float g = 0.f;
            #pragma unroll 7
            for (int mm = 0; mm < HWd; mm++) g += tp[mm];
            g_qgap[(size_t)bq*Cd + tl*64 + c] = g * (1.0f/HWd);
        }
    }
}

// ---------------- kernel 2: w2 marginals, widened (200 blocks) --------------
// block = (b,p,qg); qg owns 15 of 75 queries.
__global__ void __launch_bounds__(256) w2_kernel(const float* __restrict__ sup) {
    __shared__ float sch[32*52];
    __shared__ float gch[32*16];
    __shared__ float wb[15*HWd];
    __shared__ float rsum[15];
    const int t = threadIdx.x;
    const int bid = blockIdx.x;
    const int bp = bid / 5, qg = bid % 5;
    const int b = bp / Pd, p = bp % Pd;
    const int qbase = qg * 15;

    float acc[3] = {0.f, 0.f, 0.f};
    int qlk[3], nk[3];
    bool vk[3];
    #pragma unroll
    for (int k = 0; k < 3; k++) {
        int o = t + 256*k;
        vk[k] = o < 15*HWd;
        qlk[k] = o / HWd;
        nk[k] = o - qlk[k]*HWd;
    }

    #pragma unroll 1
    for (int ch = 0; ch < 20; ch++) {
        __syncthreads();
        for (int i = t; i < 32*HWd; i += 256) {
            int cc = i / HWd, n = i - cc*HWd;
            sch[cc*52 + n] = sup[(size_t)bp*IMG + ch*(32*HWd) + i];
        }
        for (int i = t; i < 512; i += 256) {
            int cc = i >> 4, ql = i & 15;
            gch[i] = (ql < 15)
                ? g_qgap[((size_t)b*Qd + qbase + ql)*Cd + ch*32 + cc] : 0.f;
        }
        __syncthreads();
        #pragma unroll 8
        for (int cc = 0; cc < 32; cc++) {
            #pragma unroll
            for (int k = 0; k < 3; k++)
                if (vk[k]) acc[k] += sch[cc*52 + nk[k]] * gch[cc*16 + qlk[k]];
        }
    }
    __syncthreads();
    #pragma unroll
    for (int k = 0; k < 3; k++)
        if (vk[k]) wb[t + 256*k] = (fmaxf(acc[k], 0.f) + 1e-3f) + 1e-5f;
    __syncthreads();
    if (t < 15) {
        float s = 0.f;
        for (int n = 0; n < HWd; n++) s += wb[t*HWd + n];
        rsum[t] = 1.0f / s;
    }
    __syncthreads();
    #pragma unroll
    for (int k = 0; k < 3; k++) {
        if (vk[k]) {
            int q = qbase + qlk[k];
            g_mb[(((size_t)b*Qd + q)*Pd + p)*HWd + nk[k]] = wb[t + 256*k] * rsum[qlk[k]];
        }
    }
}

// ---------------- kernel 3: packed-row cp.async double-buffered MMA GEMM ----
#define RS    36
#define A_LO_W (64*RS)
#define B_HI_W (128*RS)
#define BUF_W  (384*RS)
#define GEMM_SMEM (2*BUF_W*4)

__global__ void __launch_bounds__(256) sgemm_mma_kernel() {
    const int t = threadIdx.x;
    const int blk = blockIdx.x;
    const int b  = blk / (MT_PER_B*2);
    const int rem = blk - b*(MT_PER_B*2);
    const int mt = rem >> 1, nt = rem & 1;
    const int warp = t >> 5, lane = t & 31;
    const int wm = warp >> 2, wn = warp & 3;
    const int gid = lane >> 2, tid4 = lane & 3;

    const uint32_t smb = smem_u32(sh_dyn);
    const uint32_t* smw = (const uint32_t*)sh_dyn;

    const uint4* qh = (const uint4*)g_qbf_hi;
    const uint4* ql = (const uint4*)g_qbf_lo;
    const uint4* shv = (const uint4*)g_sbf_hi;
    const uint4* slv = (const uint4*)g_sbf_lo;

    float acc[2][4][4];
    #pragma unroll
    for (int i = 0; i < 2; i++)
        #pragma unroll
        for (int j = 0; j < 4; j++)
            #pragma unroll
            for (int k = 0; k < 4; k++) acc[i][j][k] = 0.f;

    auto stage = [&](int ch, int bufsel) {
        const uint32_t dbase = smb + (uint32_t)bufsel*(BUF_W*4);
        #pragma unroll
        for (int k = 0; k < 4; k++) {
            int i = t + k*256;
            int arr = i >> 9, remx = i & 511, row = remx >> 3, seg = remx & 7;
            int R = mt*64 + row; if (R > MROWS-1) R = MROWS-1;
            const uint4* s = (arr ? ql : qh) + ((size_t)b*MROWS + R)*80 + ch*8 + seg;
            cp_async16(dbase + (uint32_t)(arr*A_LO_W + row*RS + seg*4)*4, s);
        }
        #pragma unroll
        for (int k = 0; k < 8; k++) {
            int i = t + k*256;
            int arr = i >> 10, remx = i & 1023, row = remx >> 3, seg = remx & 7;
            int N0 = nt*128 + row; if (N0 > Nn-1) N0 = Nn-1;
            const uint4* s = (arr ? slv : shv) + ((size_t)b*Nn + N0)*80 + ch*8 + seg;
            cp_async16(dbase + (uint32_t)(B_HI_W + arr*(B_HI_W) + row*RS + seg*4)*4, s);
        }
    };

    stage(0, 0);
    CP_COMMIT();

    #pragma unroll 1
    for (int ch = 0; ch < 10; ch++) {
        if (ch < 9) { stage(ch+1, (ch+1) & 1); CP_COMMIT(); CP_WAIT1(); }
        else        { CP_WAIT0(); }
        __syncthreads();

        const uint32_t* bw = smw + (ch & 1)*BUF_W;
        #pragma unroll
        for (int ks = 0; ks < 4; ks++) {
            uint32_t ahf[2][4], alf[2][4];
            #pragma unroll
            for (int ms = 0; ms < 2; ms++) {
                int r0 = wm*32 + ms*16 + gid;
                int w0 = r0*RS + tid4 + ks*8;
                int w1 = (r0+8)*RS + tid4 + ks*8;
                ahf[ms][0] = bw[w0];        ahf[ms][1] = bw[w1];
                ahf[ms][2] = bw[w0+4];      ahf[ms][3] = bw[w1+4];
                alf[ms][0] = bw[A_LO_W+w0]; alf[ms][1] = bw[A_LO_W+w1];
                alf[ms][2] = bw[A_LO_W+w0+4]; alf[ms][3] = bw[A_LO_W+w1+4];
            }
            #pragma unroll
            for (int ns = 0; ns < 4; ns++) {
                int n0 = wn*32 + ns*8 + gid;
                int wb = B_HI_W + n0*RS + tid4 + ks*8;
                uint32_t bh0 = bw[wb], bh1 = bw[wb+4];
                uint32_t bl0 = bw[wb+B_HI_W], bl1 = bw[wb+4+B_HI_W];
                #pragma unroll
                for (int ms = 0; ms < 2; ms++) {
                    mma16816(acc[ms][ns], ahf[ms][0], ahf[ms][1], ahf[ms][2], ahf[ms][3], bh0, bh1);
                    mma16816(acc[ms][ns], ahf[ms][0], ahf[ms][1], ahf[ms][2], ahf[ms][3], bl0, bl1);
                    mma16816(acc[ms][ns], alf[ms][0], alf[ms][1], alf[ms][2], alf[ms][3], bh0, bh1);
                }
            }
        }
        __syncthreads();
    }

    #pragma unroll
    for (int ms = 0; ms < 2; ms++) {
        #pragma unroll
        for (int half = 0; half < 2; half++) {
            int R = mt*64 + wm*32 + ms*16 + gid + half*8;
            if (R >= MROWS) continue;
            int q = R / HWd, mm = R - q*HWd;
            float* dstq = g_S + ((size_t)(b*Qd + q)*Pd)*SMATS + mm*HWd;
            #pragma unroll
            for (int ns = 0; ns < 4; ns++) {
                #pragma unroll
                for (int e = 0; e < 2; e++) {
                    int C = nt*128 + wn*32 + ns*8 + tid4*2 + e;
                    if (C < Pd*HWd) {
                        int p = C / HWd, nn = C - p*HWd;
                        dstq[(size_t)p*SMATS + nn] = acc[ms][ns][half*2 + e];
                    }
                }
            }
        }
    }
}

// ---------------- kernel 4: pair-split Sinkhorn (early exit tau=1e-5) ----
__global__ void __launch_bounds__(128, 1) sinkhorn_kernel() {
    __shared__ __align__(16) float Ksh[VP2*VP2];
    __shared__ __align__(16) float ush[VP2];
    __shared__ __align__(16) float vsh[VP2];
    __shared__ float red[4];

    const int t = threadIdx.x;
    const int idx = blockIdx.x;
    const float* Sg = g_S + (size_t)idx*SMATS;

    float lmax = -1e30f;
    for (int i = t; i < HWd*HWd; i += 128) lmax = fmaxf(lmax, Sg[i]);
    #pragma unroll
    for (int o = 16; o; o >>= 1) lmax = fmaxf(lmax, __shfl_xor_sync(0xffffffffu, lmax, o));
    if ((t & 31) == 0) red[t >> 5] = lmax;
    for (int i = t; i < VP2*VP2; i += 128) Ksh[i] = 0.f;
    if (t < VP2) { vsh[t] = (t < HWd) ? 1.0f : 0.f; ush[t] = 0.f; }
    __syncthreads();
    const float Smax = fmaxf(fmaxf(red[0], red[1]), fmaxf(red[2], red[3]));

    for (int i = t; i < HWd*HWd; i += 128) {
        int m = i / HWd, n = i - m*HWd;
        Ksh[m*VP2 + n] = __expf((Sg[i] - Smax) * INV_EPS);
    }
    __syncthreads();

    const int m = t >> 1, h = t & 1;
    const bool act = m < HWd;
    float4 Kr[7], Kc[7];
    #pragma unroll
    for (int j = 0; j < 7; j++) {
        Kr[j] = make_float4(0.f, 0.f, 0.f, 0.f);
        Kc[j] = make_float4(0.f, 0.f, 0.f, 0.f);
    }
    float am = 0.f, bn = 0.f;
    if (act) {
        const float4* kr4 = (const float4*)(Ksh + m*VP2) + h*7;
        #pragma unroll
        for (int j = 0; j < 7; j++) Kr[j] = kr4[j];
        #pragma unroll
        for (int j = 0; j < 7; j++) {
            int e = h*28 + 4*j;
            Kc[j] = make_float4(Ksh[e*VP2 + m], Ksh[(e+1)*VP2 + m],
                                Ksh[(e+2)*VP2 + m], Ksh[(e+3)*VP2 + m]);
        }
        am = g_ma[(size_t)idx*HWd + m];
        bn = g_mb[(size_t)idx*HWd + m];
    }
    const float4* ub = (const float4*)ush + h*7;
    const float4* vb = (const float4*)vsh + h*7;

    float uprev = 1e30f, vprev = 1e30f;
    #pragma unroll 1
    for (int it = 0; it < S_ITERS; it++) {
        float s = dot7(Kr, vb);
        s += __shfl_xor_sync(0xffffffffu, s, 1);
        float u = __fdividef(am, s);
        if (act && h == 0) ush[m] = u;
        __syncthreads();
        float s2 = dot7(Kc, ub);
        s2 += __shfl_xor_sync(0xffffffffu, s2, 1);
        float v = __fdividef(bn, s2);
        if (act && h == 0) vsh[m] = v;
        if ((it & 3) == 3) {
            bool ok = (!act) || (fabsf(u - uprev) <= 1e-5f*fabsf(u) &&
                                 fabsf(v - vprev) <= 1e-5f*fabsf(v));
            uprev = u; vprev = v;
            if (__syncthreads_and(ok)) break;
        } else {
            __syncthreads();
        }
    }

    float part = 0.f;
    for (int i = t; i < HWd*HWd; i += 128) {
        int mm = i / HWd, nn = i - mm*HWd;
        part += Sg[i] * Ksh[mm*VP2 + nn] * ush[mm] * vsh[nn];
    }
    #pragma unroll
    for (int o = 16; o; o >>= 1) part += __shfl_xor_sync(0xffffffffu, part, o);
    if ((t & 31) == 0) red[t >> 5] = part;
    __syncthreads();
    if (t == 0) g_logits[idx] = TEMPER * ((red[0] + red[1]) + (red[2] + red[3]));
}

// ---------------- kernel 5: cross-entropy loss ----------------
__global__ void loss_kernel(const int* __restrict__ qy, float* __restrict__ out) {
    __shared__ float red[8];
    const int t = threadIdx.x;
    float s = 0.f;
    for (int r = t; r < BQd; r += 256) {
        float l[Pd];
        #pragma unroll
        for (int k = 0; k < Pd; k++) l[k] = g_logits[r*Pd + k];
        float mx = l[0];
        #pragma unroll
        for (int k = 1; k < Pd; k++) mx = fmaxf(mx, l[k]);
        float se = 0.f;
        #pragma unroll
        for (int k = 0; k < Pd; k++) se += expf(l[k] - mx);
        float lse = mx + logf(se);
        s += lse - l[qy[r]];
    }
    #pragma unroll
    for (int o = 16; o; o >>= 1) s += __shfl_xor_sync(0xffffffffu, s, o);
    if ((t & 31) == 0) red[t >> 5] = s;
    __syncthreads();
    if (t == 0) {
        float tot = 0.f;
        #pragma unroll
        for (int i = 0; i < 8; i++) tot += red[i];
        out[0] = tot * (1.0f / BQd);
    }
}

// ---------------- launch ---------------------------------------------------
extern "C" void kernel_launch(void* const* d_in, const int* in_sizes, int n_in,
                              void* d_out, int out_size) {
    const float* sup = (const float*)d_in[0];
    const float* qry = (const float*)d_in[1];
    const int*   qy  = (const int*)d_in[3];
    float* out = (float*)d_out;

    cudaFuncSetAttribute(gaps_sup, cudaFuncAttributeMaxDynamicSharedMemorySize, GAPS_SMEM);
    cudaFuncSetAttribute(sgemm_mma_kernel, cudaFuncAttributeMaxDynamicSharedMemorySize, GEMM_SMEM);

    gaps_sup<<<Bd*Pd, 512, GAPS_SMEM>>>(sup);
    prep_merged<<<Bd*Pd + BQd, 512>>>(sup, qry);
    w2_kernel<<<Bd*Pd*5, 256>>>(sup);
    sgemm_mma_kernel<<<NGBLK, 256, GEMM_SMEM>>>();
    sinkhorn_kernel<<<NMAT, 128>>>();
    loss_kernel<<<1, 256>>>(qy, out);
}